// round 7
// baseline (speedup 1.0000x reference)
#include <cuda_runtime.h>
#include <cstdint>

#define M_DIM  512
#define N_DIM  768
#define BT     64            // pair-tile side
#define NTT    8             // tiles per dimension (512/64)
#define NTILES 36            // upper-triangular tile pairs (8*9/2)
#define NSLICE 4             // K splits
#define KS     192           // k's per slice (768/4)
#define KC     32            // k's per smem chunk
#define SPAD   36            // smem row stride (floats): conflict-free b-loads
#define NB2    (NTILES * 4)  // pass2 blocks (144)

// Scratch: per-(slice,tile) 64x64 partial sum-of-squares. 2.36 MB.
__device__ float g_sumsq[NSLICE * NTILES * BT * BT];
__device__ float g_partials[NB2];
__device__ int   g_done;

__device__ __forceinline__ uint64_t pk2(float x, float y) {
    uint64_t r;
    asm("mov.b64 %0, {%1, %2};" : "=l"(r) : "f"(x), "f"(y));
    return r;
}

__device__ __forceinline__ float hsum2(uint64_t v) {
    float lo, hi;
    asm("mov.b64 {%0, %1}, %2;" : "=f"(lo), "=f"(hi) : "l"(v));
    return lo + hi;
}

// acc2 += d * relu(d)  (== relu(d)^2), d = a + (-b), two k's packed per op.
__device__ __forceinline__ void step2(uint64_t& acc, uint64_t a2, uint64_t nb2) {
    asm("{\n\t"
        ".reg .b64 d2, r2;\n\t"
        ".reg .f32 lo, hi;\n\t"
        "add.rn.f32x2 d2, %1, %2;\n\t"
        "mov.b64 {lo, hi}, d2;\n\t"
        "max.f32 lo, lo, 0f00000000;\n\t"
        "max.f32 hi, hi, 0f00000000;\n\t"
        "mov.b64 r2, {lo, hi};\n\t"
        "fma.rn.f32x2 %0, d2, r2, %0;\n\t"
        "}" : "+l"(acc) : "l"(a2), "l"(nb2));
}

__device__ __forceinline__ void unrank_tile(int t, int& ti, int& tj) {
    int r = t; ti = 0;
    while (r >= NTT - ti) { r -= NTT - ti; ti++; }
    tj = ti + r;
}

__global__ void __launch_bounds__(256, 1)
pass1_kernel(const float* __restrict__ repr, const int* __restrict__ gt32)
{
    __shared__ float As[BT][SPAD];
    __shared__ float Bs[BT][SPAD];   // negated
    __shared__ int   iIdx[BT], jIdx[BT];
    __shared__ int   odd_or;

    const int tid = threadIdx.x;
    const int b   = blockIdx.x;
    const int t   = b % NTILES;
    const int s   = b / NTILES;
    int ti, tj;
    unrank_tile(t, ti, tj);

    // --- GT dtype detection (only first 2048 bytes touched: safe either way) ---
    if (tid == 0) odd_or = 0;
    __syncthreads();
    atomicOr(&odd_or, gt32[2 * tid + 1]);   // odd words: 0 iff int64 small values
    __syncthreads();
    const bool is64 = (odd_or == 0);
    if (tid < BT) {
        int gr = ti * BT + tid;
        iIdx[tid] = is64 ? gt32[2 * gr] : gt32[gr];
    } else if (tid < 2 * BT) {
        int r  = tid - BT;
        int gr = tj * BT + r;
        jIdx[r] = is64 ? gt32[2 * gr] : gt32[gr];
    }
    __syncthreads();

    // --- staging: 64 rows x 8 float4 per chunk; 256 thr -> 2 f4 each ---
    const int lrow = tid >> 2;          // 0..63
    const int lc   = (tid & 3) * 4;     // float col 0,4,8,12 (and +16)
    const float* ap = repr + (long)iIdx[lrow] * N_DIM + s * KS + lc;
    const float* bp = repr + (long)jIdx[lrow] * N_DIM + s * KS + lc;

    const int tx = tid & 15;            // j sub-index (cols tx + 16c)
    const int ty = tid >> 4;            // i sub-index (rows ty + 16r)

    uint64_t acc[4][4];
    #pragma unroll
    for (int r = 0; r < 4; r++)
        #pragma unroll
        for (int c = 0; c < 4; c++) acc[r][c] = 0ull;

    for (int ch = 0; ch < KS / KC; ch++) {
        float4 a0 = *(const float4*)(ap);
        float4 a1 = *(const float4*)(ap + 16);
        float4 b0 = *(const float4*)(bp);
        float4 b1 = *(const float4*)(bp + 16);
        ap += KC; bp += KC;

        __syncthreads();   // prior chunk fully consumed
        *(float4*)&As[lrow][lc]      = a0;
        *(float4*)&As[lrow][lc + 16] = a1;
        b0.x = -b0.x; b0.y = -b0.y; b0.z = -b0.z; b0.w = -b0.w;
        b1.x = -b1.x; b1.y = -b1.y; b1.z = -b1.z; b1.w = -b1.w;
        *(float4*)&Bs[lrow][lc]      = b0;
        *(float4*)&Bs[lrow][lc + 16] = b1;
        __syncthreads();

        #pragma unroll
        for (int kq = 0; kq < KC / 4; kq++) {
            float4 av[4], bv[4];
            #pragma unroll
            for (int r = 0; r < 4; r++)
                av[r] = *(const float4*)&As[ty + 16 * r][kq * 4];
            #pragma unroll
            for (int c = 0; c < 4; c++)
                bv[c] = *(const float4*)&Bs[tx + 16 * c][kq * 4];

            #pragma unroll
            for (int r = 0; r < 4; r++) {
                #pragma unroll
                for (int c = 0; c < 4; c++) {
                    step2(acc[r][c], pk2(av[r].x, av[r].y), pk2(bv[c].x, bv[c].y));
                    step2(acc[r][c], pk2(av[r].z, av[r].w), pk2(bv[c].z, bv[c].w));
                }
            }
        }
    }

    float* dst = g_sumsq + (s * NTILES + t) * (BT * BT);
    #pragma unroll
    for (int r = 0; r < 4; r++)
        #pragma unroll
        for (int c = 0; c < 4; c++)
            dst[(ty + 16 * r) * BT + (tx + 16 * c)] = hsum2(acc[r][c]);
}

// Pass2: 144 blocks (36 tiles x 4 position-chunks). Each block sums sqrt of
// cross-slice sums for 1024 positions, then the last-arriving block reduces
// all 144 partials in parallel.
__global__ void __launch_bounds__(256, 1)
pass2_kernel(float* __restrict__ out)
{
    const int tid = threadIdx.x;
    const int b   = blockIdx.x;
    const int t   = b >> 2;         // tile
    const int q   = b & 3;          // position chunk
    int ti, tj;
    unrank_tile(t, ti, tj);

    const int base = (t * (BT * BT)) + q * 1024;

    float v = 0.0f;
    #pragma unroll
    for (int it = 0; it < 4; it++) {
        int p = q * 1024 + it * 256 + tid;          // 0..4095 within tile
        int off = t * (BT * BT) + p;
        float ssum = g_sumsq[0 * NTILES * BT * BT + off]
                   + g_sumsq[1 * NTILES * BT * BT + off]
                   + g_sumsq[2 * NTILES * BT * BT + off]
                   + g_sumsq[3 * NTILES * BT * BT + off];
        int gi = ti * BT + (p >> 6);
        int gj = tj * BT + (p & 63);
        if (gi < gj) v += sqrtf(ssum);
    }
    (void)base;

    #pragma unroll
    for (int o = 16; o > 0; o >>= 1)
        v += __shfl_xor_sync(0xffffffffu, v, o);

    __shared__ float wsum[8];
    __shared__ bool  amLast;
    if ((tid & 31) == 0) wsum[tid >> 5] = v;
    __syncthreads();

    if (tid == 0) {
        float blocksum = 0.0f;
        #pragma unroll
        for (int w = 0; w < 8; w++) blocksum += wsum[w];
        g_partials[b] = blocksum;
        __threadfence();
        int prev = atomicAdd(&g_done, 1);
        amLast = (prev == NB2 - 1);
    }
    __syncthreads();

    if (amLast) {
        // Parallel final reduction over 144 partials (deterministic order).
        volatile float* gp = g_partials;
        float x = (tid < NB2) ? gp[tid] : 0.0f;
        #pragma unroll
        for (int o = 16; o > 0; o >>= 1)
            x += __shfl_xor_sync(0xffffffffu, x, o);
        if ((tid & 31) == 0) wsum[tid >> 5] = x;
        __syncthreads();
        if (tid == 0) {
            float total = 0.0f;
            #pragma unroll
            for (int w = 0; w < 8; w++) total += wsum[w];
            *out = total;
            g_done = 0;     // reset for next graph replay
        }
    }
}

extern "C" void kernel_launch(void* const* d_in, const int* in_sizes, int n_in,
                              void* d_out, int out_size)
{
    const float* repr = (const float*)d_in[0];
    const int*   gt32 = (const int*)d_in[1];
    float*       out  = (float*)d_out;

    pass1_kernel<<<NTILES * NSLICE, 256>>>(repr, gt32);
    pass2_kernel<<<NB2, 256>>>(out);
}

// round 8
// speedup vs baseline: 1.2267x; 1.2267x over previous
#include <cuda_runtime.h>
#include <cstdint>

#define M_DIM  512
#define N_DIM  768
#define BT     64            // pair-tile side
#define NTT    8             // tiles per dimension (512/64)
#define NTILES 36            // upper-triangular tile pairs (8*9/2)
#define NSLICE 4             // K splits
#define KS     192           // k's per slice (768/4)
#define KC     32            // k's per smem chunk
#define SPAD   36            // smem row stride (floats): conflict-free b-loads
#define NBLK   (NTILES * NSLICE)

// Scratch: per-(slice,tile) 64x64 partial sum-of-squares. 2.36 MB (L2-resident).
__device__ float g_sumsq[NSLICE * NTILES * BT * BT];
__device__ float g_tpartial[NTILES];
__device__ int   g_tdone[NTILES];   // per-tile arrival counters (self-resetting)
__device__ int   g_done;            // tile-reducer counter (self-resetting)

__device__ __forceinline__ uint64_t pk2(float x, float y) {
    uint64_t r;
    asm("mov.b64 %0, {%1, %2};" : "=l"(r) : "f"(x), "f"(y));
    return r;
}

__device__ __forceinline__ float hsum2(uint64_t v) {
    float lo, hi;
    asm("mov.b64 {%0, %1}, %2;" : "=f"(lo), "=f"(hi) : "l"(v));
    return lo + hi;
}

// acc2 += d * relu(d)  (== relu(d)^2), d = a + (-b), two k's packed per op.
__device__ __forceinline__ void step2(uint64_t& acc, uint64_t a2, uint64_t nb2) {
    asm("{\n\t"
        ".reg .b64 d2, r2;\n\t"
        ".reg .f32 lo, hi;\n\t"
        "add.rn.f32x2 d2, %1, %2;\n\t"
        "mov.b64 {lo, hi}, d2;\n\t"
        "max.f32 lo, lo, 0f00000000;\n\t"
        "max.f32 hi, hi, 0f00000000;\n\t"
        "mov.b64 r2, {lo, hi};\n\t"
        "fma.rn.f32x2 %0, d2, r2, %0;\n\t"
        "}" : "+l"(acc) : "l"(a2), "l"(nb2));
}

__device__ __forceinline__ void unrank_tile(int t, int& ti, int& tj) {
    int r = t; ti = 0;
    while (r >= NTT - ti) { r -= NTT - ti; ti++; }
    tj = ti + r;
}

__global__ void __launch_bounds__(256, 1)
fused_kernel(const float* __restrict__ repr, const int* __restrict__ gt32,
             float* __restrict__ out)
{
    __shared__ float As[BT][SPAD];
    __shared__ float Bs[BT][SPAD];   // negated
    __shared__ int   iIdx[BT], jIdx[BT];
    __shared__ int   odd_or;
    __shared__ bool  amTileLast, amFinal;
    __shared__ float wsum[8];

    const int tid = threadIdx.x;
    const int b   = blockIdx.x;
    const int t   = b >> 2;          // tile  (slices of a tile adjacent -> finish together)
    const int s   = b & 3;           // slice
    int ti, tj;
    unrank_tile(t, ti, tj);

    // --- GT dtype detection (only first 2048 bytes touched: safe either way) ---
    if (tid == 0) odd_or = 0;
    __syncthreads();
    atomicOr(&odd_or, gt32[2 * tid + 1]);   // odd words: 0 iff int64 small values
    __syncthreads();
    const bool is64 = (odd_or == 0);
    if (tid < BT) {
        int gr = ti * BT + tid;
        iIdx[tid] = is64 ? gt32[2 * gr] : gt32[gr];
    } else if (tid < 2 * BT) {
        int r  = tid - BT;
        int gr = tj * BT + r;
        jIdx[r] = is64 ? gt32[2 * gr] : gt32[gr];
    }
    __syncthreads();

    // --- staging: 64 rows x 8 float4 per chunk; 256 thr -> 2 f4 each ---
    const int lrow = tid >> 2;          // 0..63
    const int lc   = (tid & 3) * 4;     // float col 0,4,8,12 (and +16)
    const float* ap = repr + (long)iIdx[lrow] * N_DIM + s * KS + lc;
    const float* bp = repr + (long)jIdx[lrow] * N_DIM + s * KS + lc;

    const int tx = tid & 15;            // j sub-index (cols tx + 16c)
    const int ty = tid >> 4;            // i sub-index (rows ty + 16r)

    uint64_t acc[4][4];
    #pragma unroll
    for (int r = 0; r < 4; r++)
        #pragma unroll
        for (int c = 0; c < 4; c++) acc[r][c] = 0ull;

    for (int ch = 0; ch < KS / KC; ch++) {
        float4 a0 = *(const float4*)(ap);
        float4 a1 = *(const float4*)(ap + 16);
        float4 b0 = *(const float4*)(bp);
        float4 b1 = *(const float4*)(bp + 16);
        ap += KC; bp += KC;

        __syncthreads();   // prior chunk fully consumed
        *(float4*)&As[lrow][lc]      = a0;
        *(float4*)&As[lrow][lc + 16] = a1;
        b0.x = -b0.x; b0.y = -b0.y; b0.z = -b0.z; b0.w = -b0.w;
        b1.x = -b1.x; b1.y = -b1.y; b1.z = -b1.z; b1.w = -b1.w;
        *(float4*)&Bs[lrow][lc]      = b0;
        *(float4*)&Bs[lrow][lc + 16] = b1;
        __syncthreads();

        #pragma unroll
        for (int kq = 0; kq < KC / 4; kq++) {
            float4 av[4], bv[4];
            #pragma unroll
            for (int r = 0; r < 4; r++)
                av[r] = *(const float4*)&As[ty + 16 * r][kq * 4];
            #pragma unroll
            for (int c = 0; c < 4; c++)
                bv[c] = *(const float4*)&Bs[tx + 16 * c][kq * 4];

            #pragma unroll
            for (int r = 0; r < 4; r++) {
                #pragma unroll
                for (int c = 0; c < 4; c++) {
                    step2(acc[r][c], pk2(av[r].x, av[r].y), pk2(bv[c].x, bv[c].y));
                    step2(acc[r][c], pk2(av[r].z, av[r].w), pk2(bv[c].z, bv[c].w));
                }
            }
        }
    }

    // --- publish slice partials (deterministic STG, no fp atomics) ---
    float* dst = g_sumsq + (s * NTILES + t) * (BT * BT);
    #pragma unroll
    for (int r = 0; r < 4; r++)
        #pragma unroll
        for (int c = 0; c < 4; c++)
            dst[(ty + 16 * r) * BT + (tx + 16 * c)] = hsum2(acc[r][c]);

    // --- per-tile arrival; 4th arriver reduces the tile ---
    __threadfence();
    __syncthreads();
    if (tid == 0) {
        int prev = atomicAdd(&g_tdone[t], 1);
        amTileLast = (prev == NSLICE - 1);
        if (amTileLast) g_tdone[t] = 0;     // reset for next replay
    }
    __syncthreads();

    if (amTileLast) {
        const float* base = g_sumsq + t * (BT * BT);
        const int SL = NTILES * BT * BT;
        float v = 0.0f;
        #pragma unroll
        for (int it = 0; it < 16; it++) {
            int p = it * 256 + tid;          // 0..4095
            float ssum = base[p] + base[SL + p] + base[2 * SL + p] + base[3 * SL + p];
            int gi = ti * BT + (p >> 6);
            int gj = tj * BT + (p & 63);
            if (gi < gj) v += sqrtf(ssum);
        }

        #pragma unroll
        for (int o = 16; o > 0; o >>= 1)
            v += __shfl_xor_sync(0xffffffffu, v, o);
        if ((tid & 31) == 0) wsum[tid >> 5] = v;
        __syncthreads();

        if (tid == 0) {
            float bs = 0.0f;
            #pragma unroll
            for (int w = 0; w < 8; w++) bs += wsum[w];
            g_tpartial[t] = bs;
            __threadfence();
            int prev = atomicAdd(&g_done, 1);
            amFinal = (prev == NTILES - 1);
            if (amFinal) g_done = 0;        // reset for next replay
        }
        __syncthreads();

        if (amFinal) {
            volatile float* gp = g_tpartial;
            float x = (tid < NTILES) ? gp[tid] : 0.0f;
            #pragma unroll
            for (int o = 16; o > 0; o >>= 1)
                x += __shfl_xor_sync(0xffffffffu, x, o);
            if ((tid & 31) == 0) wsum[tid >> 5] = x;
            __syncthreads();
            if (tid == 0) {
                float total = 0.0f;
                #pragma unroll
                for (int w = 0; w < 8; w++) total += wsum[w];
                *out = total;
            }
        }
    }
}

extern "C" void kernel_launch(void* const* d_in, const int* in_sizes, int n_in,
                              void* d_out, int out_size)
{
    const float* repr = (const float*)d_in[0];
    const int*   gt32 = (const int*)d_in[1];
    float*       out  = (float*)d_out;

    fused_kernel<<<NBLK, 256>>>(repr, gt32, out);
}

// round 10
// speedup vs baseline: 1.2923x; 1.0535x over previous
#include <cuda_runtime.h>
#include <cstdint>

#define M_DIM  512
#define N_DIM  768
#define BT     64            // pair-tile side
#define NTT    8             // tiles per dimension (512/64)
#define NTILES 36            // upper-triangular tile pairs (8*9/2)
#define NSLICE 8             // K splits
#define KS     96            // k's per slice (768/8)
#define KC     32            // k's per smem chunk
#define SPAD   36            // smem row stride (floats): conflict-free b-loads
#define NBLK   (NTILES * NSLICE)

// Scratch: per-(slice,tile) 64x64 partial sum-of-squares. 4.7 MB (L2-resident).
__device__ float g_sumsq[NSLICE * NTILES * BT * BT];
__device__ float g_tpartial[NTILES];
__device__ int   g_tdone[NTILES];   // per-tile arrival counters (self-resetting)
__device__ int   g_done;            // tile-reducer counter (self-resetting)

__device__ __forceinline__ uint64_t pk2(float x, float y) {
    uint64_t r;
    asm("mov.b64 %0, {%1, %2};" : "=l"(r) : "f"(x), "f"(y));
    return r;
}

__device__ __forceinline__ float hsum2(uint64_t v) {
    float lo, hi;
    asm("mov.b64 {%0, %1}, %2;" : "=f"(lo), "=f"(hi) : "l"(v));
    return lo + hi;
}

// acc2 += d * relu(d)  (== relu(d)^2), d = a + (-b), two k's packed per op.
__device__ __forceinline__ void step2(uint64_t& acc, uint64_t a2, uint64_t nb2) {
    asm("{\n\t"
        ".reg .b64 d2, r2;\n\t"
        ".reg .f32 lo, hi;\n\t"
        "add.rn.f32x2 d2, %1, %2;\n\t"
        "mov.b64 {lo, hi}, d2;\n\t"
        "max.f32 lo, lo, 0f00000000;\n\t"
        "max.f32 hi, hi, 0f00000000;\n\t"
        "mov.b64 r2, {lo, hi};\n\t"
        "fma.rn.f32x2 %0, d2, r2, %0;\n\t"
        "}" : "+l"(acc) : "l"(a2), "l"(nb2));
}

__device__ __forceinline__ void unrank_tile(int t, int& ti, int& tj) {
    int r = t; ti = 0;
    while (r >= NTT - ti) { r -= NTT - ti; ti++; }
    tj = ti + r;
}

__global__ void __launch_bounds__(256, 2)
fused_kernel(const float* __restrict__ repr, const int* __restrict__ gt32,
             float* __restrict__ out)
{
    __shared__ float As[BT][SPAD];
    __shared__ float Bs[BT][SPAD];   // negated
    __shared__ int   iIdx[BT], jIdx[BT];
    __shared__ int   odd_or;
    __shared__ bool  amTileLast, amFinal;
    __shared__ float wsum[8];

    const int tid = threadIdx.x;
    const int b   = blockIdx.x;
    const int t   = b >> 3;          // tile  (slices of a tile adjacent)
    const int s   = b & 7;           // slice
    int ti, tj;
    unrank_tile(t, ti, tj);

    // --- GT dtype detection (only first 2048 bytes touched: safe either way) ---
    if (tid == 0) odd_or = 0;
    __syncthreads();
    atomicOr(&odd_or, gt32[2 * tid + 1]);   // odd words: 0 iff int64 small values
    __syncthreads();
    const bool is64 = (odd_or == 0);
    if (tid < BT) {
        int gr = ti * BT + tid;
        iIdx[tid] = is64 ? gt32[2 * gr] : gt32[gr];
    } else if (tid < 2 * BT) {
        int r  = tid - BT;
        int gr = tj * BT + r;
        jIdx[r] = is64 ? gt32[2 * gr] : gt32[gr];
    }
    __syncthreads();

    // --- staging: 64 rows x 8 float4 per chunk; 256 thr -> 2 f4 each ---
    const int lrow = tid >> 2;          // 0..63
    const int lc   = (tid & 3) * 4;     // float col 0,4,8,12 (and +16)
    const float* ap = repr + (long)iIdx[lrow] * N_DIM + s * KS + lc;
    const float* bp = repr + (long)jIdx[lrow] * N_DIM + s * KS + lc;

    const int tx = tid & 15;            // j sub-index (cols tx + 16c)
    const int ty = tid >> 4;            // i sub-index (rows ty + 16r)

    uint64_t acc[4][4];
    #pragma unroll
    for (int r = 0; r < 4; r++)
        #pragma unroll
        for (int c = 0; c < 4; c++) acc[r][c] = 0ull;

    #pragma unroll
    for (int ch = 0; ch < KS / KC; ch++) {
        float4 a0 = *(const float4*)(ap);
        float4 a1 = *(const float4*)(ap + 16);
        float4 b0 = *(const float4*)(bp);
        float4 b1 = *(const float4*)(bp + 16);
        ap += KC; bp += KC;

        __syncthreads();   // prior chunk fully consumed
        *(float4*)&As[lrow][lc]      = a0;
        *(float4*)&As[lrow][lc + 16] = a1;
        b0.x = -b0.x; b0.y = -b0.y; b0.z = -b0.z; b0.w = -b0.w;
        b1.x = -b1.x; b1.y = -b1.y; b1.z = -b1.z; b1.w = -b1.w;
        *(float4*)&Bs[lrow][lc]      = b0;
        *(float4*)&Bs[lrow][lc + 16] = b1;
        __syncthreads();

        #pragma unroll
        for (int kq = 0; kq < KC / 4; kq++) {
            float4 av[4], bv[4];
            #pragma unroll
            for (int r = 0; r < 4; r++)
                av[r] = *(const float4*)&As[ty + 16 * r][kq * 4];
            #pragma unroll
            for (int c = 0; c < 4; c++)
                bv[c] = *(const float4*)&Bs[tx + 16 * c][kq * 4];

            #pragma unroll
            for (int r = 0; r < 4; r++) {
                #pragma unroll
                for (int c = 0; c < 4; c++) {
                    step2(acc[r][c], pk2(av[r].x, av[r].y), pk2(bv[c].x, bv[c].y));
                    step2(acc[r][c], pk2(av[r].z, av[r].w), pk2(bv[c].z, bv[c].w));
                }
            }
        }
    }

    // --- publish slice partials (deterministic STG, no fp atomics) ---
    float* dst = g_sumsq + (s * NTILES + t) * (BT * BT);
    #pragma unroll
    for (int r = 0; r < 4; r++)
        #pragma unroll
        for (int c = 0; c < 4; c++)
            dst[(ty + 16 * r) * BT + (tx + 16 * c)] = hsum2(acc[r][c]);

    // --- per-tile arrival; 8th arriver reduces the tile ---
    __threadfence();
    __syncthreads();
    if (tid == 0) {
        int prev = atomicAdd(&g_tdone[t], 1);
        amTileLast = (prev == NSLICE - 1);
        if (amTileLast) g_tdone[t] = 0;     // reset for next replay
    }
    __syncthreads();

    if (amTileLast) {
        const float* base = g_sumsq + t * (BT * BT);
        const int SL = NTILES * BT * BT;
        float v = 0.0f;
        #pragma unroll
        for (int it = 0; it < 16; it++) {
            int p = it * 256 + tid;          // 0..4095
            float ssum = 0.0f;
            #pragma unroll
            for (int sl = 0; sl < NSLICE; sl++)
                ssum += base[sl * SL + p];
            int gi = ti * BT + (p >> 6);
            int gj = tj * BT + (p & 63);
            if (gi < gj) v += sqrtf(ssum);
        }

        #pragma unroll
        for (int o = 16; o > 0; o >>= 1)
            v += __shfl_xor_sync(0xffffffffu, v, o);
        if ((tid & 31) == 0) wsum[tid >> 5] = v;
        __syncthreads();

        if (tid == 0) {
            float bs = 0.0f;
            #pragma unroll
            for (int w = 0; w < 8; w++) bs += wsum[w];
            g_tpartial[t] = bs;
            __threadfence();
            int prev = atomicAdd(&g_done, 1);
            amFinal = (prev == NTILES - 1);
            if (amFinal) g_done = 0;        // reset for next replay
        }
        __syncthreads();

        if (amFinal) {
            volatile float* gp = g_tpartial;
            float x = (tid < NTILES) ? gp[tid] : 0.0f;
            #pragma unroll
            for (int o = 16; o > 0; o >>= 1)
                x += __shfl_xor_sync(0xffffffffu, x, o);
            if ((tid & 31) == 0) wsum[tid >> 5] = x;
            __syncthreads();
            if (tid == 0) {
                float total = 0.0f;
                #pragma unroll
                for (int w = 0; w < 8; w++) total += wsum[w];
                *out = total;
            }
        }
    }
}

extern "C" void kernel_launch(void* const* d_in, const int* in_sizes, int n_in,
                              void* d_out, int out_size)
{
    const float* repr = (const float*)d_in[0];
    const int*   gt32 = (const int*)d_in[1];
    float*       out  = (float*)d_out;

    fused_kernel<<<NBLK, 256>>>(repr, gt32, out);
}